// round 10
// baseline (speedup 1.0000x reference)
#include <cuda_runtime.h>
#include <math.h>
#include <float.h>

#define Bb 2
#define Nn 2048
#define Cc 128
#define Kk 16
#define EPSf 1e-6f
#define BNEPSf 1e-5f
#define BN_TOT (Bb*Nn)          // 4096
#define BNK (Bb*Nn*Kk)          // 65536
#define CH_MAIN 272
#define CO_MAIN 256
#define CH_NBR 132
#define CH_NBR_P 144            // padded to multiple of 16 (mma K-tile)
#define CO_NBR 128
#define STATS_G 256
#define PA 132                  // smem pitch for A tiles (128 + 4)
#define PB 68                   // smem pitch for B tiles (64 + 4)

// ---------------- scratch (device globals; no allocation allowed) ----------
__device__ float g_inner[(size_t)Bb*Nn*Nn];
__device__ float g_feats[(size_t)BNK*CH_MAIN];
__device__ float g_buf1[(size_t)BNK*CO_MAIN];
__device__ float g_buf2[(size_t)BNK*CO_MAIN];
__device__ float g_descT_src[(size_t)BN_TOT*Cc];
__device__ float g_descT_dst[(size_t)BN_TOT*Cc];
__device__ float g_nbrT_src[(size_t)BN_TOT*Cc];   // [b][c][n]
__device__ float g_nbrT_dst[(size_t)BN_TOT*Cc];
__device__ float g_norm_src[BN_TOT], g_norm_dst[BN_TOT];
__device__ float g_n2_dst[BN_TOT];
__device__ float g_nbrnorm_src[BN_TOT], g_nbrnorm_dst[BN_TOT];
__device__ int   g_idx[BNK];
__device__ int   g_sidx[BNK];
__device__ float g_rowmax[BN_TOT], g_colmax[BN_TOT];
__device__ float g_sims[(size_t)4*BNK];
__device__ float g_att[(size_t)BN_TOT*CO_MAIN];
__device__ float g_h1[(size_t)BN_TOT*CO_MAIN];
__device__ float g_h2[(size_t)BN_TOT*CO_MAIN];
__device__ float g_psum[STATS_G*CO_MAIN];
__device__ float g_psq[STATS_G*CO_MAIN];
__device__ float g_scale[CO_MAIN], g_shift[CO_MAIN];
__device__ float g_w0pad[CO_NBR*CH_NBR_P];

// ---------------- transpose [B,C,N] -> [B,N,C] -----------------------------
__global__ void transpose_kernel(const float* __restrict__ in, float* __restrict__ out) {
    __shared__ float t[32][33];
    int b = blockIdx.z;
    int n0 = blockIdx.x * 32, c0 = blockIdx.y * 32;
    int x = threadIdx.x, y = threadIdx.y;
#pragma unroll
    for (int i = 0; i < 32; i += 8)
        t[y + i][x] = in[(size_t)b*Cc*Nn + (size_t)(c0 + y + i)*Nn + n0 + x];
    __syncthreads();
#pragma unroll
    for (int i = 0; i < 32; i += 8)
        out[(size_t)b*Nn*Cc + (size_t)(n0 + y + i)*Cc + c0 + x] = t[x][y + i];
}

// ---------------- per-point descriptor norms -------------------------------
__global__ void norms_kernel(const float* __restrict__ descT, float* __restrict__ nrm,
                             float* __restrict__ n2) {
    __shared__ float red[128];
    int bn = blockIdx.x; int c = threadIdx.x;
    float v = descT[(size_t)bn*Cc + c];
    red[c] = v * v; __syncthreads();
    for (int off = 64; off > 0; off >>= 1) {
        if (c < off) red[c] += red[c + off];
        __syncthreads();
    }
    if (c == 0) { float s = red[0]; if (n2) n2[bn] = s; nrm[bn] = sqrtf(s); }
}

// ---------------- weight pad [128,132] -> [128,144] ------------------------
__global__ void pad_w0_kernel(const float* __restrict__ w) {
    int i = blockIdx.x * blockDim.x + threadIdx.x;
    if (i >= CO_NBR * CH_NBR_P) return;
    int n = i / CH_NBR_P, k = i % CH_NBR_P;
    g_w0pad[i] = (k < CH_NBR) ? w[n * CH_NBR + k] : 0.f;
}

// ---------------- tf32 helpers ---------------------------------------------
__device__ __forceinline__ unsigned f2tf(float x) {
    unsigned r;
    asm("cvt.rna.tf32.f32 %0, %1;" : "=r"(r) : "f"(x));
    return r;
}

__device__ __forceinline__ void mma_tf32(float* c, unsigned a0, unsigned a1,
                                         unsigned a2, unsigned a3,
                                         unsigned b0, unsigned b1) {
    asm volatile(
        "mma.sync.aligned.m16n8k8.row.col.f32.tf32.tf32.f32 "
        "{%0,%1,%2,%3}, {%4,%5,%6,%7}, {%8,%9}, {%0,%1,%2,%3};"
        : "+f"(c[0]), "+f"(c[1]), "+f"(c[2]), "+f"(c[3])
        : "r"(a0), "r"(a1), "r"(a2), "r"(a3), "r"(b0), "r"(b1));
}

// ---------------- NT gemm via tf32 mma.sync, 3-mma precision split ---------
// C[m][n] = sum_k A[m][k] * W[n][k].  Kc must be a multiple of 16.
// Block tile 128(m) x 64(n), 8 warps (4m x 2n), warp tile 32x32.
__global__ __launch_bounds__(256, 2)
void gemm_mma_kernel(const float* __restrict__ A, const float* __restrict__ W,
                     float* __restrict__ Cm, int M, int Nc, int Kc) {
    __shared__ unsigned Ah[16][PA], Al[16][PA];
    __shared__ unsigned Bh[16][PB], Bl[16][PB];
    int m0 = blockIdx.y * 128, n0 = blockIdx.x * 64;
    int tid = threadIdx.x;
    int warp = tid >> 5, lane = tid & 31;
    int wm = warp >> 1, wn = warp & 1;        // 4 x 2 warp grid
    int g = lane >> 2, tg = lane & 3;
    int ar = tid >> 1, ak = (tid & 1) * 8;    // A tile: 128 rows x 16 k
    int br = tid >> 2, bk = (tid & 3) * 4;    // B tile: 64 rows x 16 k

    float acc[2][4][4];
#pragma unroll
    for (int i = 0; i < 2; i++)
#pragma unroll
        for (int j = 0; j < 4; j++)
#pragma unroll
            for (int l = 0; l < 4; l++) acc[i][j][l] = 0.f;

    for (int kt = 0; kt < Kc; kt += 16) {
        float4 x0 = *(const float4*)&A[(size_t)(m0 + ar) * Kc + kt + ak];
        float4 x1 = *(const float4*)&A[(size_t)(m0 + ar) * Kc + kt + ak + 4];
        float4 y  = *(const float4*)&W[(size_t)(n0 + br) * Kc + kt + bk];
        __syncthreads();   // previous tile fully consumed
        {
            float xs[8] = {x0.x, x0.y, x0.z, x0.w, x1.x, x1.y, x1.z, x1.w};
#pragma unroll
            for (int u = 0; u < 8; u++) {
                unsigned h = f2tf(xs[u]);
                float lo = xs[u] - __uint_as_float(h);
                Ah[ak + u][ar] = h;
                Al[ak + u][ar] = f2tf(lo);
            }
            float ys[4] = {y.x, y.y, y.z, y.w};
#pragma unroll
            for (int u = 0; u < 4; u++) {
                unsigned h = f2tf(ys[u]);
                float lo = ys[u] - __uint_as_float(h);
                Bh[bk + u][br] = h;
                Bl[bk + u][br] = f2tf(lo);
            }
        }
        __syncthreads();
#pragma unroll
        for (int ks = 0; ks < 16; ks += 8) {
#pragma unroll
            for (int mt = 0; mt < 2; mt++) {
                int mB = wm * 32 + mt * 16;
                unsigned ah0 = Ah[ks + tg][mB + g];
                unsigned ah1 = Ah[ks + tg][mB + g + 8];
                unsigned ah2 = Ah[ks + tg + 4][mB + g];
                unsigned ah3 = Ah[ks + tg + 4][mB + g + 8];
                unsigned al0 = Al[ks + tg][mB + g];
                unsigned al1 = Al[ks + tg][mB + g + 8];
                unsigned al2 = Al[ks + tg + 4][mB + g];
                unsigned al3 = Al[ks + tg + 4][mB + g + 8];
#pragma unroll
                for (int nt = 0; nt < 4; nt++) {
                    int nB = wn * 32 + nt * 8;
                    unsigned bh0 = Bh[ks + tg][nB + g];
                    unsigned bh1 = Bh[ks + tg + 4][nB + g];
                    unsigned bl0 = Bl[ks + tg][nB + g];
                    unsigned bl1 = Bl[ks + tg + 4][nB + g];
                    mma_tf32(acc[mt][nt], ah0, ah1, ah2, ah3, bh0, bh1);
                    mma_tf32(acc[mt][nt], ah0, ah1, ah2, ah3, bl0, bl1);
                    mma_tf32(acc[mt][nt], al0, al1, al2, al3, bh0, bh1);
                }
            }
        }
    }
#pragma unroll
    for (int mt = 0; mt < 2; mt++) {
        int row0 = m0 + wm * 32 + mt * 16 + g;
#pragma unroll
        for (int nt = 0; nt < 4; nt++) {
            int col = n0 + wn * 32 + nt * 8 + 2 * tg;
            *(float2*)&Cm[(size_t)row0 * Nc + col] =
                make_float2(acc[mt][nt][0], acc[mt][nt][1]);
            *(float2*)&Cm[(size_t)(row0 + 8) * Nc + col] =
                make_float2(acc[mt][nt][2], acc[mt][nt][3]);
        }
    }
}

// ---------------- TN gemm 128x128x8 fp32 (batched over Bb) -----------------
// C[b][m][n] = sum_k A[b][k][m]*B[b][k][n];  A,B pitch Nn.  (exact fp32 path)
__global__ void gemm_tn128_kernel(const float* __restrict__ A, const float* __restrict__ Bm,
                                  float* __restrict__ Cm, int Kc) {
    __shared__ float As[2][8][128];
    __shared__ float Bs[2][8][128];
    int b = blockIdx.z;
    const float* Ab = A + (size_t)b * Kc * Nn;
    const float* Bp = Bm + (size_t)b * Kc * Nn;
    float* Cb = Cm + (size_t)b * Nn * Nn;
    int m0 = blockIdx.y * 128, n0 = blockIdx.x * 128;
    int tid = threadIdx.x;
    int lk2 = tid >> 5;           // 0..7
    int lm = (tid & 31) * 4;
    int ty = tid >> 4, tx = tid & 15;
    float acc[8][8];
#pragma unroll
    for (int i = 0; i < 8; i++)
#pragma unroll
        for (int j = 0; j < 8; j++) acc[i][j] = 0.f;

    *(float4*)&As[0][lk2][lm] = *(const float4*)&Ab[(size_t)lk2 * Nn + m0 + lm];
    *(float4*)&Bs[0][lk2][lm] = *(const float4*)&Bp[(size_t)lk2 * Nn + n0 + lm];
    __syncthreads();
    int nb = 0;
    for (int kt = 0; kt < Kc; kt += 8) {
        bool nxt = (kt + 8) < Kc;
        float4 a2, b2;
        if (nxt) {
            a2 = *(const float4*)&Ab[(size_t)(kt + 8 + lk2) * Nn + m0 + lm];
            b2 = *(const float4*)&Bp[(size_t)(kt + 8 + lk2) * Nn + n0 + lm];
        }
#pragma unroll
        for (int kkk = 0; kkk < 8; kkk++) {
            float a[8], b[8];
            *(float4*)&a[0] = *(const float4*)&As[nb][kkk][ty * 4];
            *(float4*)&a[4] = *(const float4*)&As[nb][kkk][64 + ty * 4];
            *(float4*)&b[0] = *(const float4*)&Bs[nb][kkk][tx * 4];
            *(float4*)&b[4] = *(const float4*)&Bs[nb][kkk][64 + tx * 4];
#pragma unroll
            for (int i = 0; i < 8; i++)
#pragma unroll
                for (int j = 0; j < 8; j++) acc[i][j] = fmaf(a[i], b[j], acc[i][j]);
        }
        if (nxt) {
            int nb2 = nb ^ 1;
            *(float4*)&As[nb2][lk2][lm] = a2;
            *(float4*)&Bs[nb2][lk2][lm] = b2;
            nb = nb2;
        }
        __syncthreads();
    }
#pragma unroll
    for (int i = 0; i < 8; i++) {
        int row = m0 + ((i < 4) ? (ty * 4 + i) : (64 + ty * 4 + i - 4));
        *(float4*)&Cb[(size_t)row * Nn + n0 + tx * 4] =
            make_float4(acc[i][0], acc[i][1], acc[i][2], acc[i][3]);
        *(float4*)&Cb[(size_t)row * Nn + n0 + 64 + tx * 4] =
            make_float4(acc[i][4], acc[i][5], acc[i][6], acc[i][7]);
    }
}

// ---------------- BatchNorm stats (deterministic two-stage) ----------------
__global__ void bn_stats1_kernel(const float* __restrict__ Y, int M, int Cout) {
    int c = threadIdx.x;
    float s = 0.f, s2 = 0.f;
    for (int r = blockIdx.x; r < M; r += STATS_G) {
        float v = Y[(size_t)r*Cout + c];
        s += v; s2 += v * v;
    }
    g_psum[blockIdx.x*Cout + c] = s;
    g_psq[blockIdx.x*Cout + c]  = s2;
}

__global__ void bn_stats2_kernel(int M, int Cout, const float* __restrict__ gamma,
                                 const float* __restrict__ beta) {
    int c = threadIdx.x;
    float s = 0.f, s2 = 0.f;
    for (int g = 0; g < STATS_G; g++) { s += g_psum[g*Cout + c]; s2 += g_psq[g*Cout + c]; }
    float inv = 1.f / (float)M;
    float mu = s * inv;
    float var = fmaxf(s2 * inv - mu * mu, 0.f);
    float sc = gamma[c] * rsqrtf(var + BNEPSf);
    g_scale[c] = sc;
    g_shift[c] = beta[c] - mu * sc;
}

__global__ void bn_apply_relu_kernel(float* __restrict__ Y, int total, int cmask) {
    int i = blockIdx.x * blockDim.x + threadIdx.x;
    if (i >= total) return;
    int c = i & cmask;
    Y[i] = fmaxf(Y[i] * g_scale[c] + g_shift[c], 0.f);
}

// ---------------- KNN (descriptor space): per src query over dst -----------
__global__ void knn_desc_kernel() {
    __shared__ float key[Nn];
    __shared__ float rv[256]; __shared__ int ri[256];
    int bj = blockIdx.x; int b = bj >> 11; int j = bj & (Nn - 1);
    const float* base = g_inner + (size_t)b*Nn*Nn + j;   // column j, stride Nn
    for (int i = threadIdx.x; i < Nn; i += 256)
        key[i] = g_n2_dst[b*Nn + i] - 2.f * base[(size_t)i*Nn];
    __syncthreads();
    for (int s = 0; s < Kk; s++) {
        float bvv = FLT_MAX; int bii = Nn;
        for (int i = threadIdx.x; i < Nn; i += 256) {
            float v = key[i];
            if (v < bvv) { bvv = v; bii = i; }
        }
        rv[threadIdx.x] = bvv; ri[threadIdx.x] = bii;
        __syncthreads();
        for (int off = 128; off > 0; off >>= 1) {
            if (threadIdx.x < off) {
                float v2 = rv[threadIdx.x + off]; int i2 = ri[threadIdx.x + off];
                if (v2 < rv[threadIdx.x] ||
                    (v2 == rv[threadIdx.x] && i2 < ri[threadIdx.x])) {
                    rv[threadIdx.x] = v2; ri[threadIdx.x] = i2;
                }
            }
            __syncthreads();
        }
        if (threadIdx.x == 0) { g_idx[bj*Kk + s] = ri[0]; key[ri[0]] = FLT_MAX; }
        __syncthreads();
    }
}

// ---------------- KNN (spatial, self) --------------------------------------
__global__ void knn_spatial_kernel(const float* __restrict__ xyz, int* __restrict__ oidx) {
    __shared__ float key[Nn];
    __shared__ float rv[256]; __shared__ int ri[256];
    int bj = blockIdx.x; int b = bj >> 11;
    float qx = xyz[(size_t)bj*3 + 0], qy = xyz[(size_t)bj*3 + 1], qz = xyz[(size_t)bj*3 + 2];
    const float* xb = xyz + (size_t)b*Nn*3;
    for (int i = threadIdx.x; i < Nn; i += 256) {
        float dx = xb[i*3 + 0] - qx, dy = xb[i*3 + 1] - qy, dz = xb[i*3 + 2] - qz;
        key[i] = dx*dx + dy*dy + dz*dz;
    }
    __syncthreads();
    for (int s = 0; s < Kk; s++) {
        float bvv = FLT_MAX; int bii = Nn;
        for (int i = threadIdx.x; i < Nn; i += 256) {
            float v = key[i];
            if (v < bvv) { bvv = v; bii = i; }
        }
        rv[threadIdx.x] = bvv; ri[threadIdx.x] = bii;
        __syncthreads();
        for (int off = 128; off > 0; off >>= 1) {
            if (threadIdx.x < off) {
                float v2 = rv[threadIdx.x + off]; int i2 = ri[threadIdx.x + off];
                if (v2 < rv[threadIdx.x] ||
                    (v2 == rv[threadIdx.x] && i2 < ri[threadIdx.x])) {
                    rv[threadIdx.x] = v2; ri[threadIdx.x] = i2;
                }
            }
            __syncthreads();
        }
        if (threadIdx.x == 0) { oidx[bj*Kk + s] = ri[0]; key[ri[0]] = FLT_MAX; }
        __syncthreads();
    }
}

// ---------------- cosine row/col maxima ------------------------------------
__global__ void rowmax_kernel(const float* __restrict__ nd, const float* __restrict__ ns) {
    __shared__ float red[256];
    int bp = blockIdx.x; int b = bp >> 11;
    const float* row = g_inner + (size_t)bp*Nn;
    float ndv = nd[bp];
    const float* nsb = ns + b*Nn;
    float m = -FLT_MAX;
    for (int q = threadIdx.x; q < Nn; q += 256)
        m = fmaxf(m, row[q] / (ndv * nsb[q] + EPSf));
    red[threadIdx.x] = m; __syncthreads();
    for (int off = 128; off > 0; off >>= 1) {
        if (threadIdx.x < off) red[threadIdx.x] = fmaxf(red[threadIdx.x], red[threadIdx.x + off]);
        __syncthreads();
    }
    if (threadIdx.x == 0) g_rowmax[bp] = red[0];
}

__global__ void colmax_kernel(const float* __restrict__ nd, const float* __restrict__ ns) {
    __shared__ float sm[8][32];
    int b = blockIdx.y;
    int q = blockIdx.x * 32 + threadIdx.x;
    float nsv = ns[b*Nn + q];
    const float* colb = g_inner + (size_t)b*Nn*Nn + q;
    const float* ndb = nd + b*Nn;
    float m = -FLT_MAX;
    for (int p = threadIdx.y; p < Nn; p += 8)
        m = fmaxf(m, colb[(size_t)p*Nn] / (ndb[p] * nsv + EPSf));
    sm[threadIdx.y][threadIdx.x] = m; __syncthreads();
    if (threadIdx.y == 0) {
#pragma unroll
        for (int r = 1; r < 8; r++) m = fmaxf(m, sm[r][threadIdx.x]);
        g_colmax[b*Nn + q] = m;
    }
}

__global__ void gather_sims_kernel(const float* __restrict__ nd, const float* __restrict__ ns,
                                   float* __restrict__ s1, float* __restrict__ s2) {
    int t = blockIdx.x * blockDim.x + threadIdx.x;
    if (t >= BNK) return;
    int bn = t >> 4; int b = bn >> 11; int n = bn & (Nn - 1);
    int i = g_idx[t];
    float innv = g_inner[(size_t)(b*Nn + i)*Nn + n];
    float cosv = innv / (nd[b*Nn + i] * ns[bn] + EPSf);
    s1[t] = cosv / (g_colmax[bn] + EPSf);        // src_dst
    s2[t] = cosv / (g_rowmax[b*Nn + i] + EPSf);  // dst_src
}

// ---------------- neighbor-branch feature build (padded to 144) ------------
__global__ void build_f_kernel(const float* __restrict__ descT, const float* __restrict__ xyz) {
    int t = blockIdx.x; int c = threadIdx.x;
    if (c >= CH_NBR_P) return;
    int bn = t >> 4; int b = bn >> 11;
    int i = g_sidx[t];
    int gi = b*Nn + i;
    float* dst = g_feats + (size_t)t*CH_NBR_P;
    if (c < Cc) dst[c] = descT[(size_t)gi*Cc + c];
    else if (c < 131) { int d = c - 128; dst[c] = xyz[gi*3 + d] - xyz[bn*3 + d]; }
    else if (c == 131) {
        float dx = xyz[gi*3+0]-xyz[bn*3+0], dy = xyz[gi*3+1]-xyz[bn*3+1], dz = xyz[gi*3+2]-xyz[bn*3+2];
        dst[c] = sqrtf(dx*dx + dy*dy + dz*dz);
    }
    else dst[c] = 0.f;
}

// ---------------- neighbor-branch finalize (reads activated buf1) ----------
__global__ void nbr_finalize_kernel(const float* __restrict__ descT, float* __restrict__ nbrT,
                                    float* __restrict__ nnorm) {
    __shared__ float red[128]; __shared__ float wk[Kk];
    int bn = blockIdx.x; int b = bn >> 11; int n = bn & (Nn - 1);
    int c = threadIdx.x;
    for (int k = 0; k < Kk; k++) {
        red[c] = g_buf1[((size_t)bn*Kk + k)*CO_NBR + c];
        __syncthreads();
        for (int off = 64; off > 0; off >>= 1) {
            if (c < off) red[c] = fmaxf(red[c], red[c + off]);
            __syncthreads();
        }
        if (c == 0) wk[k] = red[0];
        __syncthreads();
    }
    if (c == 0) {
        float mx = -FLT_MAX;
        for (int k = 0; k < Kk; k++) mx = fmaxf(mx, wk[k]);
        float s = 0.f;
        for (int k = 0; k < Kk; k++) { wk[k] = expf(wk[k] - mx); s += wk[k]; }
        float is = 1.f / s;
        for (int k = 0; k < Kk; k++) wk[k] *= is;
    }
    __syncthreads();
    float acc = 0.f;
    for (int k = 0; k < Kk; k++) {
        int i = g_sidx[bn*Kk + k];
        acc += wk[k] * descT[(size_t)(b*Nn + i)*Cc + c];
    }
    nbrT[(size_t)b*Cc*Nn + (size_t)c*Nn + n] = acc;
    red[c] = acc * acc; __syncthreads();
    for (int off = 64; off > 0; off >>= 1) {
        if (c < off) red[c] += red[c + off];
        __syncthreads();
    }
    if (c == 0) nnorm[bn] = sqrtf(red[0]);
}

// ---------------- main-branch 272-ch feature build -------------------------
__global__ void build_feats_kernel(const float* __restrict__ sxyz, const float* __restrict__ dxyz,
                                   const float* __restrict__ sT, const float* __restrict__ dT,
                                   const float* __restrict__ sw, const float* __restrict__ dw) {
    int t = blockIdx.x; int c = threadIdx.x;
    if (c >= CH_MAIN) return;
    int bn = t >> 4; int b = bn >> 11;
    int i = g_idx[t];
    int gi = b*Nn + i;
    float* o = g_feats + (size_t)t*CH_MAIN;
    if (c < 3) o[c] = dxyz[gi*3 + c] - sxyz[bn*3 + c];
    else if (c == 3) {
        float dx = dxyz[gi*3+0]-sxyz[bn*3+0], dy = dxyz[gi*3+1]-sxyz[bn*3+1], dz = dxyz[gi*3+2]-sxyz[bn*3+2];
        o[3] = sqrtf(dx*dx + dy*dy + dz*dz);
    }
    else if (c < 7)   o[c] = sxyz[bn*3 + (c - 4)];
    else if (c < 10)  o[c] = dxyz[gi*3 + (c - 7)];
    else if (c < 138) o[c] = sT[(size_t)bn*Cc + (c - 10)];
    else if (c < 266) o[c] = dT[(size_t)gi*Cc + (c - 138)];
    else if (c == 266) o[c] = sw[bn];
    else if (c == 267) o[c] = dw[gi];
    else o[c] = g_sims[(size_t)(c - 268)*BNK + t];
}

// ---------------- attention pooling (reads activated buf1) -----------------
__global__ void att_finalize_kernel(const float* __restrict__ dxyz, float* __restrict__ out_corres) {
    __shared__ float red[256]; __shared__ float wk[Kk];
    int bn = blockIdx.x; int b = bn >> 11;
    int c = threadIdx.x;
    for (int k = 0; k < Kk; k++) {
        red[c] = g_buf1[((size_t)bn*Kk + k)*CO_MAIN + c];
        __syncthreads();
        for (int off = 128; off > 0; off >>= 1) {
            if (c < off) red[c] = fmaxf(red[c], red[c + off]);
            __syncthreads();
        }
        if (c == 0) wk[k] = red[0];
        __syncthreads();
    }
    if (c == 0) {
        float mx = -FLT_MAX;
        for (int k = 0; k < Kk; k++) mx = fmaxf(mx, wk[k]);
        float s = 0.f;
        for (int k = 0; k < Kk; k++) { wk[k] = expf(wk[k] - mx); s += wk[k]; }
        float is = 1.f / s;
        for (int k = 0; k < Kk; k++) wk[k] *= is;
    }
    __syncthreads();
    float acc = 0.f;
    for (int k = 0; k < Kk; k++)
        acc += wk[k] * g_buf1[((size_t)bn*Kk + k)*CO_MAIN + c];
    g_att[(size_t)bn*CO_MAIN + c] = acc;
    if (c < 3) {
        float s = 0.f;
        for (int k = 0; k < Kk; k++) {
            int i = g_idx[bn*Kk + k];
            s += wk[k] * dxyz[(b*Nn + i)*3 + c];
        }
        out_corres[bn*3 + c] = s;
    }
}

// ---------------- final sigmoid head ---------------------------------------
__global__ void mlp3_kernel(const float* __restrict__ W, const float* __restrict__ bias,
                            float* __restrict__ out) {
    __shared__ float red[256];
    int bn = blockIdx.x; int c = threadIdx.x;
    red[c] = g_h2[(size_t)bn*CO_MAIN + c] * W[c];
    __syncthreads();
    for (int off = 128; off > 0; off >>= 1) {
        if (c < off) red[c] += red[c + off];
        __syncthreads();
    }
    if (c == 0) {
        float z = red[0] + bias[0];
        out[bn] = 1.f / (1.f + expf(-z));
    }
}

// ---------------- host-side helpers ----------------------------------------
static void conv_bn_relu(const float* X, const float* W, float* Y, int M, int Cout, int Cin,
                         const float* gamma, const float* beta) {
    gemm_mma_kernel<<<dim3(Cout / 64, M / 128), 256>>>(X, W, Y, M, Cout, Cin);
    bn_stats1_kernel<<<STATS_G, Cout>>>(Y, M, Cout);
    bn_stats2_kernel<<<1, Cout>>>(M, Cout, gamma, beta);
    int total = M * Cout;
    bn_apply_relu_kernel<<<(total + 255) / 256, 256>>>(Y, total, Cout - 1);
}

extern "C" void kernel_launch(void* const* d_in, const int* in_sizes, int n_in,
                              void* d_out, int out_size) {
    const float* src_xyz  = (const float*)d_in[0];
    const float* src_desc = (const float*)d_in[1];
    const float* dst_xyz  = (const float*)d_in[2];
    const float* dst_desc = (const float*)d_in[3];
    const float* src_w    = (const float*)d_in[4];
    const float* dst_w    = (const float*)d_in[5];
    const float* c1_W0 = (const float*)d_in[6];
    const float* c1_W  = (const float*)d_in[7];
    const float* c1_g  = (const float*)d_in[8];
    const float* c1_b  = (const float*)d_in[9];
    const float* c2_W0 = (const float*)d_in[10];
    const float* c2_W  = (const float*)d_in[11];
    const float* c2_g  = (const float*)d_in[12];
    const float* c2_b  = (const float*)d_in[13];
    const float* m1_W  = (const float*)d_in[14];
    // d_in[15] m1_bias: cancels exactly under train-mode BN
    const float* m1_g  = (const float*)d_in[16];
    const float* m1_b  = (const float*)d_in[17];
    const float* m2_W  = (const float*)d_in[18];
    // d_in[19] m2_bias: cancels under BN
    const float* m2_g  = (const float*)d_in[20];
    const float* m2_b  = (const float*)d_in[21];
    const float* m3_W  = (const float*)d_in[22];
    const float* m3_bias = (const float*)d_in[23];
    float* outp = (float*)d_out;

    float *inner, *feats, *buf1, *buf2, *dTs, *dTd, *nTs, *nTd;
    float *nsrc, *ndst, *n2d, *nnsrc, *nndst, *sims, *att, *h1, *h2, *w0pad;
    int *sidxp;
    cudaGetSymbolAddress((void**)&inner, g_inner);
    cudaGetSymbolAddress((void**)&feats, g_feats);
    cudaGetSymbolAddress((void**)&buf1,  g_buf1);
    cudaGetSymbolAddress((void**)&buf2,  g_buf2);
    cudaGetSymbolAddress((void**)&dTs,   g_descT_src);
    cudaGetSymbolAddress((void**)&dTd,   g_descT_dst);
    cudaGetSymbolAddress((void**)&nTs,   g_nbrT_src);
    cudaGetSymbolAddress((void**)&nTd,   g_nbrT_dst);
    cudaGetSymbolAddress((void**)&nsrc,  g_norm_src);
    cudaGetSymbolAddress((void**)&ndst,  g_norm_dst);
    cudaGetSymbolAddress((void**)&n2d,   g_n2_dst);
    cudaGetSymbolAddress((void**)&nnsrc, g_nbrnorm_src);
    cudaGetSymbolAddress((void**)&nndst, g_nbrnorm_dst);
    cudaGetSymbolAddress((void**)&sims,  g_sims);
    cudaGetSymbolAddress((void**)&att,   g_att);
    cudaGetSymbolAddress((void**)&h1,    g_h1);
    cudaGetSymbolAddress((void**)&h2,    g_h2);
    cudaGetSymbolAddress((void**)&w0pad, g_w0pad);
    cudaGetSymbolAddress((void**)&sidxp, g_sidx);

    // Stage 0: transpose descriptors, norms, pad neighbor weight
    transpose_kernel<<<dim3(Nn/32, Cc/32, Bb), dim3(32, 8)>>>(src_desc, dTs);
    transpose_kernel<<<dim3(Nn/32, Cc/32, Bb), dim3(32, 8)>>>(dst_desc, dTd);
    norms_kernel<<<BN_TOT, 128>>>(dTs, nsrc, (float*)0);
    norms_kernel<<<BN_TOT, 128>>>(dTd, ndst, n2d);
    pad_w0_kernel<<<(CO_NBR*CH_NBR_P + 255)/256, 256>>>(c2_W0);

    // Stage 1: descriptor inner products, knn, sims 0/1 (exact fp32)
    gemm_tn128_kernel<<<dim3(Nn/128, Nn/128, Bb), 256>>>(dst_desc, src_desc, inner, Cc);
    knn_desc_kernel<<<BN_TOT, 256>>>();
    rowmax_kernel<<<BN_TOT, 256>>>(ndst, nsrc);
    colmax_kernel<<<dim3(Nn/32, Bb), dim3(32, 8)>>>(ndst, nsrc);
    gather_sims_kernel<<<BNK/256, 256>>>(ndst, nsrc, sims + 0*(size_t)BNK, sims + 1*(size_t)BNK);

    // Stage 2a: neighbor branch, src cloud
    knn_spatial_kernel<<<BN_TOT, 256>>>(src_xyz, sidxp);
    build_f_kernel<<<BNK, 160>>>(dTs, src_xyz);
    conv_bn_relu(feats, w0pad, buf1, BNK, CO_NBR, CH_NBR_P, c2_g + 0*Cc, c2_b + 0*Cc);
    conv_bn_relu(buf1, c2_W + 0*Cc*Cc, buf2, BNK, CO_NBR, Cc, c2_g + 1*Cc, c2_b + 1*Cc);
    conv_bn_relu(buf2, c2_W + 1*Cc*Cc, buf1, BNK, CO_NBR, Cc, c2_g + 2*Cc, c2_b + 2*Cc);
    nbr_finalize_kernel<<<BN_TOT, 128>>>(dTs, nTs, nnsrc);

    // Stage 2b: neighbor branch, dst cloud
    knn_spatial_kernel<<<BN_TOT, 256>>>(dst_xyz, sidxp);
    build_f_kernel<<<BNK, 160>>>(dTd, dst_xyz);
    conv_bn_relu(feats, w0pad, buf1, BNK, CO_NBR, CH_NBR_P, c2_g + 0*Cc, c2_b + 0*Cc);
    conv_bn_relu(buf1, c2_W + 0*Cc*Cc, buf2, BNK, CO_NBR, Cc, c2_g + 1*Cc, c2_b + 1*Cc);
    conv_bn_relu(buf2, c2_W + 1*Cc*Cc, buf1, BNK, CO_NBR, Cc, c2_g + 2*Cc, c2_b + 2*Cc);
    nbr_finalize_kernel<<<BN_TOT, 128>>>(dTd, nTd, nndst);

    // Stage 3: neighbor cosine sims 2/3 (reuse inner buffer; exact fp32)
    gemm_tn128_kernel<<<dim3(Nn/128, Nn/128, Bb), 256>>>(nTd, nTs, inner, Cc);
    rowmax_kernel<<<BN_TOT, 256>>>(nndst, nnsrc);
    colmax_kernel<<<dim3(Nn/32, Bb), dim3(32, 8)>>>(nndst, nnsrc);
    gather_sims_kernel<<<BNK/256, 256>>>(nndst, nnsrc, sims + 2*(size_t)BNK, sims + 3*(size_t)BNK);

    // Stage 4: main branch
    build_feats_kernel<<<BNK, 288>>>(src_xyz, dst_xyz, dTs, dTd, src_w, dst_w);
    conv_bn_relu(feats, c1_W0, buf1, BNK, CO_MAIN, CH_MAIN, c1_g + 0*CO_MAIN, c1_b + 0*CO_MAIN);
    conv_bn_relu(buf1, c1_W + 0*CO_MAIN*CO_MAIN, buf2, BNK, CO_MAIN, CO_MAIN,
                 c1_g + 1*CO_MAIN, c1_b + 1*CO_MAIN);
    conv_bn_relu(buf2, c1_W + 1*CO_MAIN*CO_MAIN, buf1, BNK, CO_MAIN, CO_MAIN,
                 c1_g + 2*CO_MAIN, c1_b + 2*CO_MAIN);
    att_finalize_kernel<<<BN_TOT, 256>>>(dst_xyz, outp);

    // Stage 5: MLP head (m1/m2 biases cancel in BN)
    conv_bn_relu(att, m1_W, h1, BN_TOT, CO_MAIN, CO_MAIN, m1_g, m1_b);
    conv_bn_relu(h1, m2_W, h2, BN_TOT, CO_MAIN, CO_MAIN, m2_g, m2_b);
    mlp3_kernel<<<BN_TOT, 256>>>(m3_W, m3_bias, outp + (size_t)BN_TOT*3);
}

// round 12
// speedup vs baseline: 1.1667x; 1.1667x over previous
#include <cuda_runtime.h>
#include <math.h>
#include <float.h>

#define Bb 2
#define Nn 2048
#define Cc 128
#define Kk 16
#define EPSf 1e-6f
#define BNEPSf 1e-5f
#define BN_TOT (Bb*Nn)          // 4096
#define BNK (Bb*Nn*Kk)          // 65536
#define CH_MAIN 272
#define CO_MAIN 256
#define CH_NBR 132
#define CO_NBR 128
#define STATS_G 256

// ---------------- scratch (device globals; no allocation allowed) ----------
__device__ float g_inner[(size_t)Bb*Nn*Nn];
__device__ float g_buf1[(size_t)BNK*CO_MAIN];
__device__ float g_buf2[(size_t)BNK*CO_MAIN];
__device__ float g_descT_src[(size_t)BN_TOT*Cc];
__device__ float g_descT_dst[(size_t)BN_TOT*Cc];
__device__ float g_nbrT_src[(size_t)BN_TOT*Cc];   // [b][c][n]
__device__ float g_nbrT_dst[(size_t)BN_TOT*Cc];
__device__ float g_norm_src[BN_TOT], g_norm_dst[BN_TOT];
__device__ float g_n2_dst[BN_TOT];
__device__ float g_nbrnorm_src[BN_TOT], g_nbrnorm_dst[BN_TOT];
__device__ int   g_idx[BNK];
__device__ int   g_sidx[BNK];
__device__ float g_rowmax[BN_TOT], g_colmax[BN_TOT];
__device__ float g_sims[(size_t)4*BNK];
__device__ float g_att[(size_t)BN_TOT*CO_MAIN];   // also reused as Pn (4096x128)
__device__ float g_h1[(size_t)BN_TOT*CO_MAIN];    // also reused as Ps
__device__ float g_h2[(size_t)BN_TOT*CO_MAIN];    // also reused as Pd
__device__ float g_psum[STATS_G*CO_MAIN];
__device__ float g_psq[STATS_G*CO_MAIN];
__device__ float g_scale[CO_MAIN], g_shift[CO_MAIN];
// packed layer-1 weight blocks
__device__ float g_W0s[CO_MAIN*Cc];     // c1_W0[:,10:138]
__device__ float g_W0d[CO_MAIN*Cc];     // c1_W0[:,138:266]
__device__ float g_W0r[CO_MAIN*16];     // c1_W0[:,{0..9,266..271}]
__device__ float g_W0nd[CO_NBR*Cc];     // c2_W0[:,0:128]
__device__ float g_W0ng[CO_NBR*4];      // c2_W0[:,128:132]

// ---------------- weight pack kernels --------------------------------------
__global__ void pack_kernel(const float* __restrict__ in, float* __restrict__ out,
                            int n, int kout, int stride, int off) {
    int i = blockIdx.x * blockDim.x + threadIdx.x;
    if (i >= n * kout) return;
    int r = i / kout, k = i % kout;
    out[i] = in[(size_t)r * stride + off + k];
}

__global__ void pack_w0r_kernel(const float* __restrict__ in) {
    int i = blockIdx.x * blockDim.x + threadIdx.x;
    if (i >= CO_MAIN * 16) return;
    int r = i >> 4, k = i & 15;
    int col = (k < 10) ? k : (k + 256);   // {0..9, 266..271}
    g_W0r[i] = in[(size_t)r * CH_MAIN + col];
}

// ---------------- transpose [B,C,N] -> [B,N,C] -----------------------------
__global__ void transpose_kernel(const float* __restrict__ in, float* __restrict__ out) {
    __shared__ float t[32][33];
    int b = blockIdx.z;
    int n0 = blockIdx.x * 32, c0 = blockIdx.y * 32;
    int x = threadIdx.x, y = threadIdx.y;
#pragma unroll
    for (int i = 0; i < 32; i += 8)
        t[y + i][x] = in[(size_t)b*Cc*Nn + (size_t)(c0 + y + i)*Nn + n0 + x];
    __syncthreads();
#pragma unroll
    for (int i = 0; i < 32; i += 8)
        out[(size_t)b*Nn*Cc + (size_t)(n0 + y + i)*Cc + c0 + x] = t[x][y + i];
}

// ---------------- per-point descriptor norms -------------------------------
__global__ void norms_kernel(const float* __restrict__ descT, float* __restrict__ nrm,
                             float* __restrict__ n2) {
    __shared__ float red[128];
    int bn = blockIdx.x; int c = threadIdx.x;
    float v = descT[(size_t)bn*Cc + c];
    red[c] = v * v; __syncthreads();
    for (int off = 64; off > 0; off >>= 1) {
        if (c < off) red[c] += red[c + off];
        __syncthreads();
    }
    if (c == 0) { float s = red[0]; if (n2) n2[bn] = s; nrm[bn] = sqrtf(s); }
}

// ---------------- NT gemm 128x128x8, 8x8/thread, double-buffered -----------
// C[m][n] = sum_k A[m][k] * W[n][k].  Kc must be a multiple of 8.
__global__ void gemm_nt128_kernel(const float* __restrict__ A, const float* __restrict__ W,
                                  float* __restrict__ Cm, int M, int Nc, int Kc) {
    __shared__ float As[2][8][128];
    __shared__ float Bs[2][8][128];
    int m0 = blockIdx.y * 128, n0 = blockIdx.x * 128;
    int tid = threadIdx.x;
    int lr = tid >> 1;            // 0..127
    int lk = (tid & 1) * 4;       // 0 or 4
    int ty = tid >> 4, tx = tid & 15;
    const float* Arow = A + (size_t)(m0 + lr) * Kc + lk;
    const float* Wrow = W + (size_t)(n0 + lr) * Kc + lk;
    float acc[8][8];
#pragma unroll
    for (int i = 0; i < 8; i++)
#pragma unroll
        for (int j = 0; j < 8; j++) acc[i][j] = 0.f;

    float4 av = *(const float4*)Arow;
    float4 bv = *(const float4*)Wrow;
    As[0][lk+0][lr] = av.x; As[0][lk+1][lr] = av.y;
    As[0][lk+2][lr] = av.z; As[0][lk+3][lr] = av.w;
    Bs[0][lk+0][lr] = bv.x; Bs[0][lk+1][lr] = bv.y;
    Bs[0][lk+2][lr] = bv.z; Bs[0][lk+3][lr] = bv.w;
    __syncthreads();
    int nb = 0;
    for (int kt = 0; kt < Kc; kt += 8) {
        bool nxt = (kt + 8) < Kc;
        float4 a2, b2;
        if (nxt) {
            a2 = *(const float4*)(Arow + kt + 8);
            b2 = *(const float4*)(Wrow + kt + 8);
        }
#pragma unroll
        for (int kkk = 0; kkk < 8; kkk++) {
            float a[8], b[8];
            *(float4*)&a[0] = *(const float4*)&As[nb][kkk][ty * 4];
            *(float4*)&a[4] = *(const float4*)&As[nb][kkk][64 + ty * 4];
            *(float4*)&b[0] = *(const float4*)&Bs[nb][kkk][tx * 4];
            *(float4*)&b[4] = *(const float4*)&Bs[nb][kkk][64 + tx * 4];
#pragma unroll
            for (int i = 0; i < 8; i++)
#pragma unroll
                for (int j = 0; j < 8; j++) acc[i][j] = fmaf(a[i], b[j], acc[i][j]);
        }
        if (nxt) {
            int nb2 = nb ^ 1;
            As[nb2][lk+0][lr] = a2.x; As[nb2][lk+1][lr] = a2.y;
            As[nb2][lk+2][lr] = a2.z; As[nb2][lk+3][lr] = a2.w;
            Bs[nb2][lk+0][lr] = b2.x; Bs[nb2][lk+1][lr] = b2.y;
            Bs[nb2][lk+2][lr] = b2.z; Bs[nb2][lk+3][lr] = b2.w;
            nb = nb2;
        }
        __syncthreads();
    }
#pragma unroll
    for (int i = 0; i < 8; i++) {
        int row = m0 + ((i < 4) ? (ty * 4 + i) : (64 + ty * 4 + i - 4));
        *(float4*)&Cm[(size_t)row * Nc + n0 + tx * 4] =
            make_float4(acc[i][0], acc[i][1], acc[i][2], acc[i][3]);
        *(float4*)&Cm[(size_t)row * Nc + n0 + 64 + tx * 4] =
            make_float4(acc[i][4], acc[i][5], acc[i][6], acc[i][7]);
    }
}

// ---------------- TN gemm 128x128x8 (batched over Bb) ----------------------
__global__ void gemm_tn128_kernel(const float* __restrict__ A, const float* __restrict__ Bm,
                                  float* __restrict__ Cm, int Kc) {
    __shared__ float As[2][8][128];
    __shared__ float Bs[2][8][128];
    int b = blockIdx.z;
    const float* Ab = A + (size_t)b * Kc * Nn;
    const float* Bp = Bm + (size_t)b * Kc * Nn;
    float* Cb = Cm + (size_t)b * Nn * Nn;
    int m0 = blockIdx.y * 128, n0 = blockIdx.x * 128;
    int tid = threadIdx.x;
    int lk2 = tid >> 5;
    int lm = (tid & 31) * 4;
    int ty = tid >> 4, tx = tid & 15;
    float acc[8][8];
#pragma unroll
    for (int i = 0; i < 8; i++)
#pragma unroll
        for (int j = 0; j < 8; j++) acc[i][j] = 0.f;

    *(float4*)&As[0][lk2][lm] = *(const float4*)&Ab[(size_t)lk2 * Nn + m0 + lm];
    *(float4*)&Bs[0][lk2][lm] = *(const float4*)&Bp[(size_t)lk2 * Nn + n0 + lm];
    __syncthreads();
    int nb = 0;
    for (int kt = 0; kt < Kc; kt += 8) {
        bool nxt = (kt + 8) < Kc;
        float4 a2, b2;
        if (nxt) {
            a2 = *(const float4*)&Ab[(size_t)(kt + 8 + lk2) * Nn + m0 + lm];
            b2 = *(const float4*)&Bp[(size_t)(kt + 8 + lk2) * Nn + n0 + lm];
        }
#pragma unroll
        for (int kkk = 0; kkk < 8; kkk++) {
            float a[8], b[8];
            *(float4*)&a[0] = *(const float4*)&As[nb][kkk][ty * 4];
            *(float4*)&a[4] = *(const float4*)&As[nb][kkk][64 + ty * 4];
            *(float4*)&b[0] = *(const float4*)&Bs[nb][kkk][tx * 4];
            *(float4*)&b[4] = *(const float4*)&Bs[nb][kkk][64 + tx * 4];
#pragma unroll
            for (int i = 0; i < 8; i++)
#pragma unroll
                for (int j = 0; j < 8; j++) acc[i][j] = fmaf(a[i], b[j], acc[i][j]);
        }
        if (nxt) {
            int nb2 = nb ^ 1;
            *(float4*)&As[nb2][lk2][lm] = a2;
            *(float4*)&Bs[nb2][lk2][lm] = b2;
            nb = nb2;
        }
        __syncthreads();
    }
#pragma unroll
    for (int i = 0; i < 8; i++) {
        int row = m0 + ((i < 4) ? (ty * 4 + i) : (64 + ty * 4 + i - 4));
        *(float4*)&Cb[(size_t)row * Nn + n0 + tx * 4] =
            make_float4(acc[i][0], acc[i][1], acc[i][2], acc[i][3]);
        *(float4*)&Cb[(size_t)row * Nn + n0 + 64 + tx * 4] =
            make_float4(acc[i][4], acc[i][5], acc[i][6], acc[i][7]);
    }
}

// ---------------- layer-1 combine kernels ----------------------------------
// Main: Y[t][o] = Ps[bn][o] + Pd[gi][o] + sum_r W0r[o][r]*rest[r]
__global__ void main_l1_combine_kernel(const float* __restrict__ sxyz,
                                       const float* __restrict__ dxyz,
                                       const float* __restrict__ sw,
                                       const float* __restrict__ dw,
                                       const float* __restrict__ Ps,
                                       const float* __restrict__ Pd,
                                       float* __restrict__ Y) {
    __shared__ float rest[16];
    int t = blockIdx.x;
    int bn = t >> 4; int b = bn >> 11;
    int i = g_idx[t]; int gi = b*Nn + i;
    int o = threadIdx.x;
    if (o == 0) {
        float sx = sxyz[bn*3+0], sy = sxyz[bn*3+1], sz = sxyz[bn*3+2];
        float kx = dxyz[gi*3+0], ky = dxyz[gi*3+1], kz = dxyz[gi*3+2];
        float dx = kx - sx, dy = ky - sy, dz = kz - sz;
        rest[0] = dx; rest[1] = dy; rest[2] = dz;
        rest[3] = sqrtf(dx*dx + dy*dy + dz*dz);
        rest[4] = sx; rest[5] = sy; rest[6] = sz;
        rest[7] = kx; rest[8] = ky; rest[9] = kz;
        rest[10] = sw[bn]; rest[11] = dw[gi];
        rest[12] = g_sims[0*(size_t)BNK + t];
        rest[13] = g_sims[1*(size_t)BNK + t];
        rest[14] = g_sims[2*(size_t)BNK + t];
        rest[15] = g_sims[3*(size_t)BNK + t];
    }
    __syncthreads();
    float acc = Ps[(size_t)bn*CO_MAIN + o] + Pd[(size_t)gi*CO_MAIN + o];
    const float4* w = (const float4*)&g_W0r[o * 16];
#pragma unroll
    for (int r = 0; r < 4; r++) {
        float4 wv = w[r];
        acc += wv.x*rest[r*4+0] + wv.y*rest[r*4+1] + wv.z*rest[r*4+2] + wv.w*rest[r*4+3];
    }
    Y[(size_t)t*CO_MAIN + o] = acc;
}

// Neighbor: Y[t][o] = Pn[gi][o] + W0ng[o][0..3] . [rela, dist]
__global__ void nbr_l1_combine_kernel(const float* __restrict__ xyz,
                                      const float* __restrict__ Pn,
                                      float* __restrict__ Y) {
    __shared__ float rest[4];
    int t = blockIdx.x;
    int bn = t >> 4; int b = bn >> 11;
    int i = g_sidx[t]; int gi = b*Nn + i;
    int o = threadIdx.x;
    if (o == 0) {
        float dx = xyz[gi*3+0] - xyz[bn*3+0];
        float dy = xyz[gi*3+1] - xyz[bn*3+1];
        float dz = xyz[gi*3+2] - xyz[bn*3+2];
        rest[0] = dx; rest[1] = dy; rest[2] = dz;
        rest[3] = sqrtf(dx*dx + dy*dy + dz*dz);
    }
    __syncthreads();
    float4 wv = *(const float4*)&g_W0ng[o * 4];
    float acc = Pn[(size_t)gi*CO_NBR + o]
              + wv.x*rest[0] + wv.y*rest[1] + wv.z*rest[2] + wv.w*rest[3];
    Y[(size_t)t*CO_NBR + o] = acc;
}

// ---------------- BatchNorm stats (deterministic two-stage) ----------------
__global__ void bn_stats1_kernel(const float* __restrict__ Y, int M, int Cout) {
    int c = threadIdx.x;
    float s = 0.f, s2 = 0.f;
    for (int r = blockIdx.x; r < M; r += STATS_G) {
        float v = Y[(size_t)r*Cout + c];
        s += v; s2 += v * v;
    }
    g_psum[blockIdx.x*Cout + c] = s;
    g_psq[blockIdx.x*Cout + c]  = s2;
}

__global__ void bn_stats2_kernel(int M, int Cout, const float* __restrict__ gamma,
                                 const float* __restrict__ beta) {
    int c = threadIdx.x;
    float s = 0.f, s2 = 0.f;
    for (int g = 0; g < STATS_G; g++) { s += g_psum[g*Cout + c]; s2 += g_psq[g*Cout + c]; }
    float inv = 1.f / (float)M;
    float mu = s * inv;
    float var = fmaxf(s2 * inv - mu * mu, 0.f);
    float sc = gamma[c] * rsqrtf(var + BNEPSf);
    g_scale[c] = sc;
    g_shift[c] = beta[c] - mu * sc;
}

__global__ void bn_apply_relu_kernel(float* __restrict__ Y, int total, int cmask) {
    int i = blockIdx.x * blockDim.x + threadIdx.x;
    if (i >= total) return;
    int c = i & cmask;
    Y[i] = fmaxf(Y[i] * g_scale[c] + g_shift[c], 0.f);
}

// ---------------- KNN (descriptor space) -----------------------------------
__global__ void knn_desc_kernel() {
    __shared__ float key[Nn];
    __shared__ float rv[256]; __shared__ int ri[256];
    int bj = blockIdx.x; int b = bj >> 11; int j = bj & (Nn - 1);
    const float* base = g_inner + (size_t)b*Nn*Nn + j;
    for (int i = threadIdx.x; i < Nn; i += 256)
        key[i] = g_n2_dst[b*Nn + i] - 2.f * base[(size_t)i*Nn];
    __syncthreads();
    for (int s = 0; s < Kk; s++) {
        float bvv = FLT_MAX; int bii = Nn;
        for (int i = threadIdx.x; i < Nn; i += 256) {
            float v = key[i];
            if (v < bvv) { bvv = v; bii = i; }
        }
        rv[threadIdx.x] = bvv; ri[threadIdx.x] = bii;
        __syncthreads();
        for (int off = 128; off > 0; off >>= 1) {
            if (threadIdx.x < off) {
                float v2 = rv[threadIdx.x + off]; int i2 = ri[threadIdx.x + off];
                if (v2 < rv[threadIdx.x] ||
                    (v2 == rv[threadIdx.x] && i2 < ri[threadIdx.x])) {
                    rv[threadIdx.x] = v2; ri[threadIdx.x] = i2;
                }
            }
            __syncthreads();
        }
        if (threadIdx.x == 0) { g_idx[bj*Kk + s] = ri[0]; key[ri[0]] = FLT_MAX; }
        __syncthreads();
    }
}

// ---------------- KNN (spatial, self) --------------------------------------
__global__ void knn_spatial_kernel(const float* __restrict__ xyz, int* __restrict__ oidx) {
    __shared__ float key[Nn];
    __shared__ float rv[256]; __shared__ int ri[256];
    int bj = blockIdx.x; int b = bj >> 11;
    float qx = xyz[(size_t)bj*3 + 0], qy = xyz[(size_t)bj*3 + 1], qz = xyz[(size_t)bj*3 + 2];
    const float* xb = xyz + (size_t)b*Nn*3;
    for (int i = threadIdx.x; i < Nn; i += 256) {
        float dx = xb[i*3 + 0] - qx, dy = xb[i*3 + 1] - qy, dz = xb[i*3 + 2] - qz;
        key[i] = dx*dx + dy*dy + dz*dz;
    }
    __syncthreads();
    for (int s = 0; s < Kk; s++) {
        float bvv = FLT_MAX; int bii = Nn;
        for (int i = threadIdx.x; i < Nn; i += 256) {
            float v = key[i];
            if (v < bvv) { bvv = v; bii = i; }
        }
        rv[threadIdx.x] = bvv; ri[threadIdx.x] = bii;
        __syncthreads();
        for (int off = 128; off > 0; off >>= 1) {
            if (threadIdx.x < off) {
                float v2 = rv[threadIdx.x + off]; int i2 = ri[threadIdx.x + off];
                if (v2 < rv[threadIdx.x] ||
                    (v2 == rv[threadIdx.x] && i2 < ri[threadIdx.x])) {
                    rv[threadIdx.x] = v2; ri[threadIdx.x] = i2;
                }
            }
            __syncthreads();
        }
        if (threadIdx.x == 0) { oidx[bj*Kk + s] = ri[0]; key[ri[0]] = FLT_MAX; }
        __syncthreads();
    }
}

// ---------------- cosine row/col maxima ------------------------------------
__global__ void rowmax_kernel(const float* __restrict__ nd, const float* __restrict__ ns) {
    __shared__ float red[256];
    int bp = blockIdx.x; int b = bp >> 11;
    const float* row = g_inner + (size_t)bp*Nn;
    float ndv = nd[bp];
    const float* nsb = ns + b*Nn;
    float m = -FLT_MAX;
    for (int q = threadIdx.x; q < Nn; q += 256)
        m = fmaxf(m, row[q] / (ndv * nsb[q] + EPSf));
    red[threadIdx.x] = m; __syncthreads();
    for (int off = 128; off > 0; off >>= 1) {
        if (threadIdx.x < off) red[threadIdx.x] = fmaxf(red[threadIdx.x], red[threadIdx.x + off]);
        __syncthreads();
    }
    if (threadIdx.x == 0) g_rowmax[bp] = red[0];
}

__global__ void colmax_kernel(const float* __restrict__ nd, const float* __restrict__ ns) {
    __shared__ float sm[8][32];
    int b = blockIdx.y;
    int q = blockIdx.x * 32 + threadIdx.x;
    float nsv = ns[b*Nn + q];
    const float* colb = g_inner + (size_t)b*Nn*Nn + q;
    const float* ndb = nd + b*Nn;
    float m = -FLT_MAX;
    for (int p = threadIdx.y; p < Nn; p += 8)
        m = fmaxf(m, colb[(size_t)p*Nn] / (ndb[p] * nsv + EPSf));
    sm[threadIdx.y][threadIdx.x] = m; __syncthreads();
    if (threadIdx.y == 0) {
#pragma unroll
        for (int r = 1; r < 8; r++) m = fmaxf(m, sm[r][threadIdx.x]);
        g_colmax[b*Nn + q] = m;
    }
}

__global__ void gather_sims_kernel(const float* __restrict__ nd, const float* __restrict__ ns,
                                   float* __restrict__ s1, float* __restrict__ s2) {
    int t = blockIdx.x * blockDim.x + threadIdx.x;
    if (t >= BNK) return;
    int bn = t >> 4; int b = bn >> 11; int n = bn & (Nn - 1);
    int i = g_idx[t];
    float innv = g_inner[(size_t)(b*Nn + i)*Nn + n];
    float cosv = innv / (nd[b*Nn + i] * ns[bn] + EPSf);
    s1[t] = cosv / (g_colmax[bn] + EPSf);        // src_dst
    s2[t] = cosv / (g_rowmax[b*Nn + i] + EPSf);  // dst_src
}

// ---------------- neighbor-branch finalize (reads activated buf1) ----------
__global__ void nbr_finalize_kernel(const float* __restrict__ descT, float* __restrict__ nbrT,
                                    float* __restrict__ nnorm) {
    __shared__ float red[128]; __shared__ float wk[Kk];
    int bn = blockIdx.x; int b = bn >> 11; int n = bn & (Nn - 1);
    int c = threadIdx.x;
    for (int k = 0; k < Kk; k++) {
        red[c] = g_buf1[((size_t)bn*Kk + k)*CO_NBR + c];
        __syncthreads();
        for (int off = 64; off > 0; off >>= 1) {
            if (c < off) red[c] = fmaxf(red[c], red[c + off]);
            __syncthreads();
        }
        if (c == 0) wk[k] = red[0];
        __syncthreads();
    }
    if (c == 0) {
        float mx = -FLT_MAX;
        for (int k = 0; k < Kk; k++) mx = fmaxf(mx, wk[k]);
        float s = 0.f;
        for (int k = 0; k < Kk; k++) { wk[k] = expf(wk[k] - mx); s += wk[k]; }
        float is = 1.f / s;
        for (int k = 0; k < Kk; k++) wk[k] *= is;
    }
    __syncthreads();
    float acc = 0.f;
    for (int k = 0; k < Kk; k++) {
        int i = g_sidx[bn*Kk + k];
        acc += wk[k] * descT[(size_t)(b*Nn + i)*Cc + c];
    }
    nbrT[(size_t)b*Cc*Nn + (size_t)c*Nn + n] = acc;
    red[c] = acc * acc; __syncthreads();
    for (int off = 64; off > 0; off >>= 1) {
        if (c < off) red[c] += red[c + off];
        __syncthreads();
    }
    if (c == 0) nnorm[bn] = sqrtf(red[0]);
}

// ---------------- attention pooling (reads activated buf1) -----------------
__global__ void att_finalize_kernel(const float* __restrict__ dxyz, float* __restrict__ out_corres) {
    __shared__ float red[256]; __shared__ float wk[Kk];
    int bn = blockIdx.x; int b = bn >> 11;
    int c = threadIdx.x;
    for (int k = 0; k < Kk; k++) {
        red[c] = g_buf1[((size_t)bn*Kk + k)*CO_MAIN + c];
        __syncthreads();
        for (int off = 128; off > 0; off >>= 1) {
            if (c < off) red[c] = fmaxf(red[c], red[c + off]);
            __syncthreads();
        }
        if (c == 0) wk[k] = red[0];
        __syncthreads();
    }
    if (c == 0) {
        float mx = -FLT_MAX;
        for (int k = 0; k < Kk; k++) mx = fmaxf(mx, wk[k]);
        float s = 0.f;
        for (int k = 0; k < Kk; k++) { wk[k] = expf(wk[k] - mx); s += wk[k]; }
        float is = 1.f / s;
        for (int k = 0; k < Kk; k++) wk[k] *= is;
    }
    __syncthreads();
    float acc = 0.f;
    for (int k = 0; k < Kk; k++)
        acc += wk[k] * g_buf1[((size_t)bn*Kk + k)*CO_MAIN + c];
    g_att[(size_t)bn*CO_MAIN + c] = acc;
    if (c < 3) {
        float s = 0.f;
        for (int k = 0; k < Kk; k++) {
            int i = g_idx[bn*Kk + k];
            s += wk[k] * dxyz[(b*Nn + i)*3 + c];
        }
        out_corres[bn*3 + c] = s;
    }
}

// ---------------- final sigmoid head ---------------------------------------
__global__ void mlp3_kernel(const float* __restrict__ W, const float* __restrict__ bias,
                            float* __restrict__ out) {
    __shared__ float red[256];
    int bn = blockIdx.x; int c = threadIdx.x;
    red[c] = g_h2[(size_t)bn*CO_MAIN + c] * W[c];
    __syncthreads();
    for (int off = 128; off > 0; off >>= 1) {
        if (c < off) red[c] += red[c + off];
        __syncthreads();
    }
    if (c == 0) {
        float z = red[0] + bias[0];
        out[bn] = 1.f / (1.f + expf(-z));
    }
}

// ---------------- host-side helpers ----------------------------------------
static void bn_and_apply(float* Y, int M, int Cout, const float* gamma, const float* beta) {
    bn_stats1_kernel<<<STATS_G, Cout>>>(Y, M, Cout);
    bn_stats2_kernel<<<1, Cout>>>(M, Cout, gamma, beta);
    int total = M * Cout;
    bn_apply_relu_kernel<<<(total + 255) / 256, 256>>>(Y, total, Cout - 1);
}

static void conv_bn_relu(const float* X, const float* W, float* Y, int M, int Cout, int Cin,
                         const float* gamma, const float* beta) {
    gemm_nt128_kernel<<<dim3(Cout / 128, M / 128), 256>>>(X, W, Y, M, Cout, Cin);
    bn_and_apply(Y, M, Cout, gamma, beta);
}

extern "C" void kernel_launch(void* const* d_in, const int* in_sizes, int n_in,
                              void* d_out, int out_size) {
    const float* src_xyz  = (const float*)d_in[0];
    const float* src_desc = (const float*)d_in[1];
    const float* dst_xyz  = (const float*)d_in[2];
    const float* dst_desc = (const float*)d_in[3];
    const float* src_w    = (const float*)d_in[4];
    const float* dst_w    = (const float*)d_in[5];
    const float* c1_W0 = (const float*)d_in[6];
    const float* c1_W  = (const float*)d_in[7];
    const float* c1_g  = (const float*)d_in[8];
    const float* c1_b  = (const float*)d_in[9];
    const float* c2_W0 = (const float*)d_in[10];
    const float* c2_W  = (const float*)d_in[11];
    const float* c2_g  = (const float*)d_in[12];
    const float* c2_b  = (const float*)d_in[13];
    const float* m1_W  = (const float*)d_in[14];
    // d_in[15] m1_bias: cancels exactly under train-mode BN
    const float* m1_g  = (const float*)d_in[16];
    const float* m1_b  = (const float*)d_in[17];
    const float* m2_W  = (const float*)d_in[18];
    // d_in[19] m2_bias: cancels under BN
    const float* m2_g  = (const float*)d_in[20];
    const float* m2_b  = (const float*)d_in[21];
    const float* m3_W  = (const float*)d_in[22];
    const float* m3_bias = (const float*)d_in[23];
    float* outp = (float*)d_out;

    float *inner, *buf1, *buf2, *dTs, *dTd, *nTs, *nTd;
    float *nsrc, *ndst, *n2d, *nnsrc, *nndst, *sims, *att, *h1, *h2;
    float *W0s, *W0d, *W0nd, *W0ng;
    int *sidxp;
    cudaGetSymbolAddress((void**)&inner, g_inner);
    cudaGetSymbolAddress((void**)&buf1,  g_buf1);
    cudaGetSymbolAddress((void**)&buf2,  g_buf2);
    cudaGetSymbolAddress((void**)&dTs,   g_descT_src);
    cudaGetSymbolAddress((void**)&dTd,   g_descT_dst);
    cudaGetSymbolAddress((void**)&nTs,   g_nbrT_src);
    cudaGetSymbolAddress((void**)&nTd,   g_nbrT_dst);
    cudaGetSymbolAddress((void**)&nsrc,  g_norm_src);
    cudaGetSymbolAddress((void**)&ndst,  g_norm_dst);
    cudaGetSymbolAddress((void**)&n2d,   g_n2_dst);
    cudaGetSymbolAddress((void**)&nnsrc, g_nbrnorm_src);
    cudaGetSymbolAddress((void**)&nndst, g_nbrnorm_dst);
    cudaGetSymbolAddress((void**)&sims,  g_sims);
    cudaGetSymbolAddress((void**)&att,   g_att);
    cudaGetSymbolAddress((void**)&h1,    g_h1);
    cudaGetSymbolAddress((void**)&h2,    g_h2);
    cudaGetSymbolAddress((void**)&W0s,   g_W0s);
    cudaGetSymbolAddress((void**)&W0d,   g_W0d);
    cudaGetSymbolAddress((void**)&W0nd,  g_W0nd);
    cudaGetSymbolAddress((void**)&W0ng,  g_W0ng);
    cudaGetSymbolAddress((void**)&sidxp, g_sidx);

    // Stage 0: transpose descriptors, norms, pack layer-1 weight blocks
    transpose_kernel<<<dim3(Nn/32, Cc/32, Bb), dim3(32, 8)>>>(src_desc, dTs);
    transpose_kernel<<<dim3(Nn/32, Cc/32, Bb), dim3(32, 8)>>>(dst_desc, dTd);
    norms_kernel<<<BN_TOT, 128>>>(dTs, nsrc, (float*)0);
    norms_kernel<<<BN_TOT, 128>>>(dTd, ndst, n2d);
    pack_kernel<<<(CO_MAIN*Cc + 255)/256, 256>>>(c1_W0, W0s, CO_MAIN, Cc, CH_MAIN, 10);
    pack_kernel<<<(CO_MAIN*Cc + 255)/256, 256>>>(c1_W0, W0d, CO_MAIN, Cc, CH_MAIN, 138);
    pack_w0r_kernel<<<(CO_MAIN*16 + 255)/256, 256>>>(c1_W0);
    pack_kernel<<<(CO_NBR*Cc + 255)/256, 256>>>(c2_W0, W0nd, CO_NBR, Cc, CH_NBR, 0);
    pack_kernel<<<(CO_NBR*4 + 255)/256, 256>>>(c2_W0, W0ng, CO_NBR, 4, CH_NBR, 128);

    // Stage 1: descriptor inner products, knn, sims 0/1 (exact fp32)
    gemm_tn128_kernel<<<dim3(Nn/128, Nn/128, Bb), 256>>>(dst_desc, src_desc, inner, Cc);
    knn_desc_kernel<<<BN_TOT, 256>>>();
    rowmax_kernel<<<BN_TOT, 256>>>(ndst, nsrc);
    colmax_kernel<<<dim3(Nn/32, Bb), dim3(32, 8)>>>(ndst, nsrc);
    gather_sims_kernel<<<BNK/256, 256>>>(ndst, nsrc, sims + 0*(size_t)BNK, sims + 1*(size_t)BNK);

    // Stage 2a: neighbor branch, src cloud  (layer1 = Pn gather + geo combine)
    knn_spatial_kernel<<<BN_TOT, 256>>>(src_xyz, sidxp);
    gemm_nt128_kernel<<<dim3(1, BN_TOT/128), 256>>>(dTs, W0nd, att /*Pn*/, BN_TOT, CO_NBR, Cc);
    nbr_l1_combine_kernel<<<BNK, CO_NBR>>>(src_xyz, att, buf1);
    bn_and_apply(buf1, BNK, CO_NBR, c2_g + 0*Cc, c2_b + 0*Cc);
    conv_bn_relu(buf1, c2_W + 0*Cc*Cc, buf2, BNK, CO_NBR, Cc, c2_g + 1*Cc, c2_b + 1*Cc);
    conv_bn_relu(buf2, c2_W + 1*Cc*Cc, buf1, BNK, CO_NBR, Cc, c2_g + 2*Cc, c2_b + 2*Cc);
    nbr_finalize_kernel<<<BN_TOT, 128>>>(dTs, nTs, nnsrc);

    // Stage 2b: neighbor branch, dst cloud
    knn_spatial_kernel<<<BN_TOT, 256>>>(dst_xyz, sidxp);
    gemm_nt128_kernel<<<dim3(1, BN_TOT/128), 256>>>(dTd, W0nd, att /*Pn*/, BN_TOT, CO_NBR, Cc);
    nbr_l1_combine_kernel<<<BNK, CO_NBR>>>(dst_xyz, att, buf1);
    bn_and_apply(buf1, BNK, CO_NBR, c2_g + 0*Cc, c2_b + 0*Cc);
    conv_bn_relu(buf1, c2_W + 0*Cc*Cc, buf2, BNK, CO_NBR, Cc, c2_g + 1*Cc, c2_b + 1*Cc);
    conv_bn_relu(buf2, c2_W + 1*Cc*Cc, buf1, BNK, CO_NBR, Cc, c2_g + 2*Cc, c2_b + 2*Cc);
    nbr_finalize_kernel<<<BN_TOT, 128>>>(dTd, nTd, nndst);

    // Stage 3: neighbor cosine sims 2/3 (exact fp32)
    gemm_tn128_kernel<<<dim3(Nn/128, Nn/128, Bb), 256>>>(nTd, nTs, inner, Cc);
    rowmax_kernel<<<BN_TOT, 256>>>(nndst, nnsrc);
    colmax_kernel<<<dim3(Nn/32, Bb), dim3(32, 8)>>>(nndst, nnsrc);
    gather_sims_kernel<<<BNK/256, 256>>>(nndst, nnsrc, sims + 2*(size_t)BNK, sims + 3*(size_t)BNK);

    // Stage 4: main branch (layer1 = Ps/Pd gathers + 16-ch combine)
    gemm_nt128_kernel<<<dim3(CO_MAIN/128, BN_TOT/128), 256>>>(dTs, W0s, h1 /*Ps*/, BN_TOT, CO_MAIN, Cc);
    gemm_nt128_kernel<<<dim3(CO_MAIN/128, BN_TOT/128), 256>>>(dTd, W0d, h2 /*Pd*/, BN_TOT, CO_MAIN, Cc);
    main_l1_combine_kernel<<<BNK, CO_MAIN>>>(src_xyz, dst_xyz, src_w, dst_w, h1, h2, buf1);
    bn_and_apply(buf1, BNK, CO_MAIN, c1_g + 0*CO_MAIN, c1_b + 0*CO_MAIN);
    conv_bn_relu(buf1, c1_W + 0*CO_MAIN*CO_MAIN, buf2, BNK, CO_MAIN, CO_MAIN,
                 c1_g + 1*CO_MAIN, c1_b + 1*CO_MAIN);
    conv_bn_relu(buf2, c1_W + 1*CO_MAIN*CO_MAIN, buf1, BNK, CO_MAIN, CO_MAIN,
                 c1_g + 2*CO_MAIN, c1_b + 2*CO_MAIN);
    att_finalize_kernel<<<BN_TOT, 256>>>(dst_xyz, outp);

    // Stage 5: MLP head (m1/m2 biases cancel in BN)
    conv_bn_relu(att, m1_W, h1, BN_TOT, CO_MAIN, CO_MAIN, m1_g, m1_b);
    conv_bn_relu(h1, m2_W, h2, BN_TOT, CO_MAIN, CO_MAIN, m2_g, m2_b);
    mlp3_kernel<<<BN_TOT, 256>>>(m3_W, m3_bias, outp + (size_t)BN_TOT*3);
}